// round 9
// baseline (speedup 1.0000x reference)
#include <cuda_runtime.h>
#include <cuda_fp16.h>
#include <math.h>
#include <stdint.h>

// Problem constants: N rows up to 100000, MUL=128, x row = 512 floats.
#define MAXN 100000
#define SQ2F 1.41421356237309515f

// Scratch (allocation-free rule: __device__ globals). fp16 for GEMM-facing data.
__device__ __half g_scal [(size_t)MAXN * 384];
__device__ __half g_h    [(size_t)MAXN * 384];
__device__ __half g_gates[(size_t)MAXN * 640];
__device__ __half g_vg   [(size_t)MAXN * 256 * 3];
// Packed (transposed to [N,K] K-major, fp16) weights.
__device__ __half g_w1p[384 * 384];
__device__ __half g_w2p[640 * 384];
__device__ __half g_wsp[128 * 384];
__device__ __half g_wvp[128 * 256];

__device__ __forceinline__ float silu_f(float v) { return v / (1.0f + expf(-v)); }

__device__ __forceinline__ uint32_t smem_u32(const void* p) {
    uint32_t a;
    asm("{ .reg .u64 t; cvta.to.shared.u64 t, %1; cvt.u32.u64 %0, t; }" : "=r"(a) : "l"(p));
    return a;
}

__device__ __forceinline__ void cp16(uint32_t dst, const void* src, int sz) {
    asm volatile("cp.async.cg.shared.global [%0], [%1], 16, %2;"
                 :: "r"(dst), "l"(src), "r"(sz) : "memory");
}

#define MMA16816(d, a0, a1, a2, a3, b0, b1)                                  \
    asm volatile(                                                            \
        "mma.sync.aligned.m16n8k16.row.col.f32.f16.f16.f32 "                 \
        "{%0,%1,%2,%3}, {%4,%5,%6,%7}, {%8,%9}, {%0,%1,%2,%3};\n"            \
        : "+f"((d)[0]), "+f"((d)[1]), "+f"((d)[2]), "+f"((d)[3])             \
        : "r"(a0), "r"(a1), "r"(a2), "r"(a3), "r"(b0), "r"(b1))

// ---------------------------------------------------------------------------
// Weight pack: Wp[n*K + k] = fp16(W[k*ldw + n]); keep first Ncols columns.
// ---------------------------------------------------------------------------
__global__ void pack_w_kernel(const float* __restrict__ W, __half* __restrict__ Wp,
                              int K, int Ncols, int ldw) {
    int idx = blockIdx.x * blockDim.x + threadIdx.x;
    if (idx >= Ncols * K) return;
    int n = idx / K;
    int k = idx - n * K;
    Wp[idx] = __float2half(W[(size_t)k * ldw + n]);
}

// ---------------------------------------------------------------------------
// K1: scal[n,384] = [s, s*s, |v|^2] in fp16.
// ---------------------------------------------------------------------------
__global__ void prep_scal_kernel(const float* __restrict__ x, __half* __restrict__ scal, int n) {
    int idx = blockIdx.x * blockDim.x + threadIdx.x;
    if (idx >= n * 128) return;
    int row = idx >> 7;
    int u = idx & 127;
    const float* xr = x + (size_t)row * 512;
    float s  = xr[u];
    float v0 = xr[128 + u * 3 + 0];
    float v1 = xr[128 + u * 3 + 1];
    float v2 = xr[128 + u * 3 + 2];
    __half* sr = scal + (size_t)row * 384;
    sr[u]       = __float2half(s);
    sr[128 + u] = __float2half(s * s);
    sr[256 + u] = __float2half(v0 * v0 + v1 * v1 + v2 * v2);
}

// ---------------------------------------------------------------------------
// FP16 mma.sync GEMM (fp32 acc), pipelined (R6 version — scalar LDS frags).
//   C[M, ncols*128] = A[M,K] @ Bp^T, Bp packed [N,K] row-major.
// Block 128x128, BK=32, 3-stage cp.async, 4 warps (2x2 of 64x64 warp tiles).
// ---------------------------------------------------------------------------
#define TILE_HALVES 5120            // 128*40
#define STAGE_HALVES 10240          // A tile + B tile

template <bool SILU, typename OT>
__global__ __launch_bounds__(128) void gemm_fp16_kernel(
    const __half* __restrict__ A, int lda, long long bsA,
    const __half* __restrict__ Bp,
    OT* __restrict__ C, int ldc, long long bsC,
    int M, int K)
{
    extern __shared__ __half smh[];
    const uint32_t sb = smem_u32(smh);

    A += (size_t)blockIdx.z * bsA;
    C += (size_t)blockIdx.z * bsC;

    const int tid  = threadIdx.x;
    const int w    = tid >> 5;
    const int lane = tid & 31;
    const int g    = lane >> 2;
    const int tg   = lane & 3;
    const int wm   = (w & 1) * 64;
    const int wn   = (w >> 1) * 64;
    const int rowBase = blockIdx.y * 128;
    const int colBase = blockIdx.x * 128;
    const int T = K >> 5;

    auto load_stage = [&](int s, int kt) {
        const int k0 = kt << 5;
        const uint32_t ab = sb + (uint32_t)(s * STAGE_HALVES) * 2u;
        const uint32_t bb = ab + TILE_HALVES * 2u;
#pragma unroll
        for (int i = 0; i < 4; i++) {
            int flat = i * 128 + tid;
            int r = flat >> 2;
            int c = flat & 3;
            uint32_t so = (uint32_t)(r * 40 + c * 8) * 2u;
            int gr = rowBase + r;
            const __half* srcA = A + (size_t)(gr < M ? gr : 0) * lda + k0 + c * 8;
            cp16(ab + so, srcA, gr < M ? 16 : 0);
            const __half* srcB = Bp + (size_t)(colBase + r) * K + k0 + c * 8;
            cp16(bb + so, srcB, 16);
        }
        asm volatile("cp.async.commit_group;" ::: "memory");
    };

    float acc[4][8][4];
#pragma unroll
    for (int mt = 0; mt < 4; mt++)
#pragma unroll
        for (int nt = 0; nt < 8; nt++)
#pragma unroll
            for (int i = 0; i < 4; i++) acc[mt][nt][i] = 0.0f;

    load_stage(0, 0);
    load_stage(1, 1);

    for (int kt = 0; kt < T; kt++) {
        const int s = kt % 3;
        if (kt + 1 < T) asm volatile("cp.async.wait_group 1;" ::: "memory");
        else            asm volatile("cp.async.wait_group 0;" ::: "memory");
        __syncthreads();
        if (kt + 2 < T) load_stage((kt + 2) % 3, kt + 2);

        const uint32_t* aw = reinterpret_cast<const uint32_t*>(smh + s * STAGE_HALVES);
        const uint32_t* bw = aw + (TILE_HALVES / 2);
#pragma unroll
        for (int kf = 0; kf < 2; kf++) {
            const int kb = kf * 8;
            unsigned a[4][4], b[8][2];
#pragma unroll
            for (int mt = 0; mt < 4; mt++) {
                const uint32_t* ap = aw + (wm + mt * 16 + g) * 20 + kb + tg;
                a[mt][0] = ap[0];
                a[mt][1] = ap[8 * 20];
                a[mt][2] = ap[4];
                a[mt][3] = ap[8 * 20 + 4];
            }
#pragma unroll
            for (int nt = 0; nt < 8; nt++) {
                const uint32_t* bp = bw + (wn + nt * 8 + g) * 20 + kb + tg;
                b[nt][0] = bp[0];
                b[nt][1] = bp[4];
            }
#pragma unroll
            for (int mt = 0; mt < 4; mt++)
#pragma unroll
                for (int nt = 0; nt < 8; nt++)
                    MMA16816(acc[mt][nt], a[mt][0], a[mt][1], a[mt][2], a[mt][3],
                             b[nt][0], b[nt][1]);
        }
        __syncthreads();
    }

#pragma unroll
    for (int mt = 0; mt < 4; mt++) {
        int r0 = rowBase + wm + mt * 16 + g;
#pragma unroll
        for (int nt = 0; nt < 8; nt++) {
            int c0 = colBase + wn + nt * 8 + 2 * tg;
            float2 lo = make_float2(acc[mt][nt][0], acc[mt][nt][1]);
            float2 hi = make_float2(acc[mt][nt][2], acc[mt][nt][3]);
            if (SILU) {
                lo.x = silu_f(lo.x); lo.y = silu_f(lo.y);
                hi.x = silu_f(hi.x); hi.y = silu_f(hi.y);
            }
            if (r0 < M) {
                OT* cr = C + (size_t)r0 * ldc + c0;
                if (sizeof(OT) == 2) *reinterpret_cast<__half2*>(cr) = __float22half2_rn(lo);
                else                 *reinterpret_cast<float2*>(cr) = lo;
            }
            if (r0 + 8 < M) {
                OT* cr = C + (size_t)(r0 + 8) * ldc + c0;
                if (sizeof(OT) == 2) *reinterpret_cast<__half2*>(cr) = __float22half2_rn(hi);
                else                 *reinterpret_cast<float2*>(cr) = hi;
            }
        }
    }
}

// ---------------------------------------------------------------------------
// K4: gate scal in place and build gated vec planes (fp16 in/out).
// ---------------------------------------------------------------------------
__global__ void gate_prep_kernel(const float* __restrict__ x, const __half* __restrict__ gates,
                                 __half* __restrict__ scal, __half* __restrict__ vg, int n) {
    int idx = blockIdx.x * blockDim.x + threadIdx.x;
    if (idx >= n * 384) return;
    int row = idx / 384;
    int j = idx - row * 384;
    const __half* g = gates + (size_t)row * 640;
    scal[idx] = __float2half(__half2float(scal[idx]) * __half2float(g[j]));
    if (j < 128) {
        int u = j;
        const float* xr = x + (size_t)row * 512;
        float s  = xr[u];
        float g1 = __half2float(g[384 + u]);
        float c2 = SQ2F * s * __half2float(g[512 + u]);
#pragma unroll
        for (int i = 0; i < 3; i++) {
            float vi = xr[128 + u * 3 + i];
            __half* vgp = vg + ((size_t)i * n + row) * 256;
            vgp[u]       = __float2half(vi * g1);
            vgp[128 + u] = __float2half(vi * c2);
        }
    }
}

// ---------------------------------------------------------------------------
// Fused output kernel: per CTA of 32 rows, 4 warps:
//   warp i<3: vo_i[32,128] = vg_i[32,256] @ Wvp^T   (K=256, 8 BK32 steps)
//   warp 3  : outs[32,128] = scal[32,384] @ Wsp^T   (K=384, 12 BK32 steps)
// Then in-CTA: residuals from x (staged in smem), scalar layernorm (warp 3,
// intra-warp), vector RMS (cross-warp ssq via smem), assemble final 512-col
// rows in smem, coalesced float4 store to out. Kills outs/outv buffers.
// ---------------------------------------------------------------------------
#define FS_STAGE 15360              // halves per stage
#define FS_AS   0
#define FS_AV0  1280
#define FS_BS   5120
#define FS_BV   10240
#define FS_SMEM (3 * FS_STAGE * 2)  // 92160 bytes

__global__ __launch_bounds__(128) void fused_out_kernel(
    const __half* __restrict__ scal, const __half* __restrict__ vg,
    const __half* __restrict__ wsp, const __half* __restrict__ wvp,
    const float* __restrict__ x, float* __restrict__ out, int n)
{
    extern __shared__ __half smh[];
    const uint32_t sb = smem_u32(smh);

    const int tid  = threadIdx.x;
    const int w    = tid >> 5;
    const int lane = tid & 31;
    const int g    = lane >> 2;
    const int tg   = lane & 3;
    const int rb   = blockIdx.x * 32;

    auto load_stage = [&](int s, int kt) {
        const int k0 = kt << 5;
        const uint32_t base = sb + (uint32_t)(s * FS_STAGE) * 2u;
        // A tiles: 32 rows x 4 chunks each (128 chunks -> 1/thread)
        {
            int r = tid >> 2, c = tid & 3;
            int gr = rb + r;
            int ok = (gr < n) ? 16 : 0;
            uint32_t so = (uint32_t)(r * 40 + c * 8) * 2u;
            const __half* sA = scal + (size_t)(gr < n ? gr : 0) * 384 + k0 + c * 8;
            cp16(base + FS_AS * 2u + so, sA, ok);
            if (k0 < 256) {
#pragma unroll
                for (int i = 0; i < 3; i++) {
                    const __half* sV = vg + ((size_t)i * n + (gr < n ? gr : 0)) * 256 + k0 + c * 8;
                    cp16(base + (uint32_t)(FS_AV0 + 1280 * i) * 2u + so, sV, ok);
                }
            }
        }
        // B tiles: 128 rows x 4 chunks = 512 chunks (4/thread)
#pragma unroll
        for (int it = 0; it < 4; it++) {
            int j = it * 128 + tid;
            int r = j >> 2, c = j & 3;
            uint32_t so = (uint32_t)(r * 40 + c * 8) * 2u;
            cp16(base + FS_BS * 2u + so, wsp + (size_t)r * 384 + k0 + c * 8, 16);
            if (k0 < 256)
                cp16(base + FS_BV * 2u + so, wvp + (size_t)r * 256 + k0 + c * 8, 16);
        }
        asm volatile("cp.async.commit_group;" ::: "memory");
    };

    float acc[2][16][4];
#pragma unroll
    for (int mt = 0; mt < 2; mt++)
#pragma unroll
        for (int nt = 0; nt < 16; nt++)
#pragma unroll
            for (int i = 0; i < 4; i++) acc[mt][nt][i] = 0.0f;

    const int aoff = (w == 3) ? FS_AS : (FS_AV0 + 1280 * w);
    const int boff = (w == 3) ? FS_BS : FS_BV;

    load_stage(0, 0);
    load_stage(1, 1);

    for (int kt = 0; kt < 12; kt++) {
        const int s = kt % 3;
        if (kt + 1 < 12) asm volatile("cp.async.wait_group 1;" ::: "memory");
        else             asm volatile("cp.async.wait_group 0;" ::: "memory");
        __syncthreads();
        if (kt + 2 < 12) load_stage((kt + 2) % 3, kt + 2);

        if (w == 3 || kt < 8) {
            const uint32_t* aw = reinterpret_cast<const uint32_t*>(smh + s * FS_STAGE + aoff);
            const uint32_t* bw = reinterpret_cast<const uint32_t*>(smh + s * FS_STAGE + boff);
#pragma unroll
            for (int kf = 0; kf < 2; kf++) {
                const int kb = kf * 8;
                unsigned a[2][4];
#pragma unroll
                for (int mt = 0; mt < 2; mt++) {
                    const uint32_t* ap = aw + (mt * 16 + g) * 20 + kb + tg;
                    a[mt][0] = ap[0];
                    a[mt][1] = ap[8 * 20];
                    a[mt][2] = ap[4];
                    a[mt][3] = ap[8 * 20 + 4];
                }
#pragma unroll
                for (int nt = 0; nt < 16; nt++) {
                    const uint32_t* bp = bw + (nt * 8 + g) * 20 + kb + tg;
                    unsigned b0 = bp[0], b1 = bp[4];
#pragma unroll
                    for (int mt = 0; mt < 2; mt++)
                        MMA16816(acc[mt][nt], a[mt][0], a[mt][1], a[mt][2], a[mt][3], b0, b1);
                }
            }
        }
        __syncthreads();
    }

    // ---- Stage x block into smem (reuses pipeline memory) ----
    float* xb = reinterpret_cast<float*>(smh);          // 32 x 512 fp32 = 64KB
    float* ssqv = xb + 32 * 512;                        // [3][32]
    {
        float4 zero = make_float4(0.f, 0.f, 0.f, 0.f);
#pragma unroll
        for (int it = 0; it < 32; it++) {
            int j = it * 128 + tid;                     // 0..4095
            int r = j >> 7;
            float4 v = (rb + r < n)
                ? reinterpret_cast<const float4*>(x + (size_t)(rb + r) * 512)[j & 127]
                : zero;
            reinterpret_cast<float4*>(xb)[j] = v;
        }
    }
    __syncthreads();

    // ---- Phase 1: residuals + per-row stats ----
    if (w < 3) {
#pragma unroll
        for (int mt = 0; mt < 2; mt++) {
#pragma unroll
            for (int h = 0; h < 2; h++) {
                int row = mt * 16 + h * 8 + g;
                const float* xr = xb + row * 512 + 128;
                float p = 0.f;
#pragma unroll
                for (int nt = 0; nt < 16; nt++) {
                    int c0 = nt * 8 + 2 * tg;
                    float v0 = acc[mt][nt][2 * h]     + xr[c0 * 3 + w];
                    float v1 = acc[mt][nt][2 * h + 1] + xr[(c0 + 1) * 3 + w];
                    acc[mt][nt][2 * h]     = v0;
                    acc[mt][nt][2 * h + 1] = v1;
                    p += v0 * v0 + v1 * v1;
                }
                p += __shfl_xor_sync(0xffffffffu, p, 1);
                p += __shfl_xor_sync(0xffffffffu, p, 2);
                if (tg == 0) ssqv[w * 32 + row] = p;
            }
        }
    } else {
#pragma unroll
        for (int mt = 0; mt < 2; mt++) {
#pragma unroll
            for (int h = 0; h < 2; h++) {
                int row = mt * 16 + h * 8 + g;
                float* xr = xb + row * 512;
                float sum = 0.f, sq = 0.f;
#pragma unroll
                for (int nt = 0; nt < 16; nt++) {
                    int c0 = nt * 8 + 2 * tg;
                    float v0 = acc[mt][nt][2 * h]     + xr[c0];
                    float v1 = acc[mt][nt][2 * h + 1] + xr[c0 + 1];
                    acc[mt][nt][2 * h]     = v0;
                    acc[mt][nt][2 * h + 1] = v1;
                    sum += v0 + v1;
                    sq  += v0 * v0 + v1 * v1;
                }
                sum += __shfl_xor_sync(0xffffffffu, sum, 1);
                sum += __shfl_xor_sync(0xffffffffu, sum, 2);
                sq  += __shfl_xor_sync(0xffffffffu, sq, 1);
                sq  += __shfl_xor_sync(0xffffffffu, sq, 2);
                float m   = sum * (1.0f / 128.0f);
                float var = fmaxf(sq * (1.0f / 128.0f) - m * m, 0.0f);
                float inv = 1.0f / (sqrtf(var) + 1e-6f);
#pragma unroll
                for (int nt = 0; nt < 16; nt++) {
                    int c0 = nt * 8 + 2 * tg;
                    xr[c0]     = (acc[mt][nt][2 * h]     - m) * inv;
                    xr[c0 + 1] = (acc[mt][nt][2 * h + 1] - m) * inv;
                }
            }
        }
    }
    __syncthreads();

    // ---- Phase 2: vector RMS normalize, write into smem row image ----
    if (w < 3) {
#pragma unroll
        for (int mt = 0; mt < 2; mt++) {
#pragma unroll
            for (int h = 0; h < 2; h++) {
                int row = mt * 16 + h * 8 + g;
                float t = ssqv[row] + ssqv[32 + row] + ssqv[64 + row];
                float vinv = 1.0f / (sqrtf(t * (1.0f / 128.0f)) + 1e-6f);
                float* xr = xb + row * 512 + 128;
#pragma unroll
                for (int nt = 0; nt < 16; nt++) {
                    int c0 = nt * 8 + 2 * tg;
                    xr[c0 * 3 + w]       = acc[mt][nt][2 * h]     * vinv;
                    xr[(c0 + 1) * 3 + w] = acc[mt][nt][2 * h + 1] * vinv;
                }
            }
        }
    }
    __syncthreads();

    // ---- Coalesced store ----
#pragma unroll
    for (int it = 0; it < 32; it++) {
        int j = it * 128 + tid;
        int r = j >> 7;
        if (rb + r < n)
            reinterpret_cast<float4*>(out + (size_t)(rb + r) * 512)[j & 127] =
                reinterpret_cast<const float4*>(xb)[j];
    }
}

// ---------------------------------------------------------------------------
extern "C" void kernel_launch(void* const* d_in, const int* in_sizes, int n_in,
                              void* d_out, int out_size) {
    const float* x  = (const float*)d_in[0];
    const float* W1 = (const float*)d_in[1];   // [384,384]
    const float* W2 = (const float*)d_in[2];   // [384,768] (cols 640:768 dead)
    const float* Ws = (const float*)d_in[3];   // [384,128]
    const float* Wv = (const float*)d_in[4];   // [256,128]
    float* out = (float*)d_out;
    int n = in_sizes[0] / 512;

    __half *scal, *h, *gates, *vg, *w1p, *w2p, *wsp, *wvp;
    cudaGetSymbolAddress((void**)&scal,  g_scal);
    cudaGetSymbolAddress((void**)&h,     g_h);
    cudaGetSymbolAddress((void**)&gates, g_gates);
    cudaGetSymbolAddress((void**)&vg,    g_vg);
    cudaGetSymbolAddress((void**)&w1p,   g_w1p);
    cudaGetSymbolAddress((void**)&w2p,   g_w2p);
    cudaGetSymbolAddress((void**)&wsp,   g_wsp);
    cudaGetSymbolAddress((void**)&wvp,   g_wvp);

    const int SMEM_BYTES = 3 * STAGE_HALVES * 2;   // 61440
    cudaFuncSetAttribute((const void*)gemm_fp16_kernel<true, __half>,
                         cudaFuncAttributeMaxDynamicSharedMemorySize, SMEM_BYTES);
    cudaFuncSetAttribute((const void*)fused_out_kernel,
                         cudaFuncAttributeMaxDynamicSharedMemorySize, FS_SMEM);

    int mblocks = (n + 127) / 128;

    // Pack weights -> [N,K] K-major fp16.
    pack_w_kernel<<<(384 * 384 + 255) / 256, 256>>>(W1, w1p, 384, 384, 384);
    pack_w_kernel<<<(640 * 384 + 255) / 256, 256>>>(W2, w2p, 384, 640, 768);
    pack_w_kernel<<<(128 * 384 + 255) / 256, 256>>>(Ws, wsp, 384, 128, 128);
    pack_w_kernel<<<(128 * 256 + 255) / 256, 256>>>(Wv, wvp, 256, 128, 128);

    // K1: scal features (fp16)
    prep_scal_kernel<<<(n * 128 + 255) / 256, 256>>>(x, scal, n);

    // G1: h = silu(scal @ W1) -> fp16
    dim3 g1(3, mblocks, 1);
    gemm_fp16_kernel<true, __half><<<g1, 128, SMEM_BYTES>>>(
        scal, 384, 0LL, w1p, h, 384, 0LL, n, 384);

    // G2: gates = silu(h @ W2[:, :640]) -> fp16
    dim3 g2(5, mblocks, 1);
    gemm_fp16_kernel<true, __half><<<g2, 128, SMEM_BYTES>>>(
        h, 384, 0LL, w2p, gates, 640, 0LL, n, 384);

    // K4: gate scal in-place, build vg planes
    gate_prep_kernel<<<(n * 384 + 255) / 256, 256>>>(x, gates, scal, vg, n);

    // Fused output: G5 + G6 + residuals + norms + store
    fused_out_kernel<<<(n + 31) / 32, 128, FS_SMEM>>>(scal, vg, wsp, wvp, x, out, n);
}

// round 10
// speedup vs baseline: 1.1426x; 1.1426x over previous
#include <cuda_runtime.h>
#include <cuda_fp16.h>
#include <math.h>
#include <stdint.h>

// Problem constants: N rows up to 100000, MUL=128, x row = 512 floats.
#define MAXN 100000
#define SQ2F 1.41421356237309515f

// Scratch (allocation-free rule: __device__ globals). fp16 for GEMM-facing data.
__device__ __half g_scal [(size_t)MAXN * 384];
__device__ __half g_h    [(size_t)MAXN * 384];
__device__ __half g_gates[(size_t)MAXN * 256];   // only vector gates (cols 384:640 of G2)
__device__ __half g_vg   [(size_t)MAXN * 256 * 3];
__device__ __half g_outs [(size_t)MAXN * 128];
__device__ __half g_outv [(size_t)MAXN * 128 * 3];
// Packed (transposed to [N,K] K-major, fp16) weights.
__device__ __half g_w1p[384 * 384];
__device__ __half g_w2p[640 * 384];
__device__ __half g_wsp[128 * 384];
__device__ __half g_wvp[128 * 256];

__device__ __forceinline__ float silu_f(float v) { return v / (1.0f + expf(-v)); }

__device__ __forceinline__ uint32_t smem_u32(const void* p) {
    uint32_t a;
    asm("{ .reg .u64 t; cvta.to.shared.u64 t, %1; cvt.u32.u64 %0, t; }" : "=r"(a) : "l"(p));
    return a;
}

__device__ __forceinline__ void cp16(uint32_t dst, const void* src, int sz) {
    asm volatile("cp.async.cg.shared.global [%0], [%1], 16, %2;"
                 :: "r"(dst), "l"(src), "r"(sz) : "memory");
}

#define MMA16816(d, a0, a1, a2, a3, b0, b1)                                  \
    asm volatile(                                                            \
        "mma.sync.aligned.m16n8k16.row.col.f32.f16.f16.f32 "                 \
        "{%0,%1,%2,%3}, {%4,%5,%6,%7}, {%8,%9}, {%0,%1,%2,%3};\n"            \
        : "+f"((d)[0]), "+f"((d)[1]), "+f"((d)[2]), "+f"((d)[3])             \
        : "r"(a0), "r"(a1), "r"(a2), "r"(a3), "r"(b0), "r"(b1))

// ---------------------------------------------------------------------------
// Weight pack: Wp[n*K + k] = fp16(W[k*ldw + n]); keep first Ncols columns.
// ---------------------------------------------------------------------------
__global__ void pack_w_kernel(const float* __restrict__ W, __half* __restrict__ Wp,
                              int K, int Ncols, int ldw) {
    int idx = blockIdx.x * blockDim.x + threadIdx.x;
    if (idx >= Ncols * K) return;
    int n = idx / K;
    int k = idx - n * K;
    Wp[idx] = __float2half(W[(size_t)k * ldw + n]);
}

// ---------------------------------------------------------------------------
// K1: scal[n,384] = [s, s*s, |v|^2] in fp16.
// ---------------------------------------------------------------------------
__global__ void prep_scal_kernel(const float* __restrict__ x, __half* __restrict__ scal, int n) {
    int idx = blockIdx.x * blockDim.x + threadIdx.x;
    if (idx >= n * 128) return;
    int row = idx >> 7;
    int u = idx & 127;
    const float* xr = x + (size_t)row * 512;
    float s  = xr[u];
    float v0 = xr[128 + u * 3 + 0];
    float v1 = xr[128 + u * 3 + 1];
    float v2 = xr[128 + u * 3 + 2];
    __half* sr = scal + (size_t)row * 384;
    sr[u]       = __float2half(s);
    sr[128 + u] = __float2half(s * s);
    sr[256 + u] = __float2half(v0 * v0 + v1 * v1 + v2 * v2);
}

// ---------------------------------------------------------------------------
// FP16 mma.sync GEMM (fp32 acc), pipelined (R6 mainloop — scalar LDS frags).
//   C[M, ncols*128] = A[M,K] @ Bp^T, Bp packed [N,K] row-major.
// Block 128x128, BK=32, 3-stage cp.async, 4 warps (2x2 of 64x64 warp tiles).
// MODE 0: plain store to C (OT half or float).
// MODE 1: silu then store to C.
// MODE 2: G2 fusion — colBase<384: scal *= silu(acc) in place (RMW);
//                     colBase>=384: gates[row*256 + col-384] = silu(acc).
// ---------------------------------------------------------------------------
#define TILE_HALVES 5120            // 128*40
#define STAGE_HALVES 10240          // A tile + B tile

template <int MODE, typename OT>
__global__ __launch_bounds__(128) void gemm_fp16_kernel(
    const __half* __restrict__ A, int lda, long long bsA,
    const __half* __restrict__ Bp,
    OT* __restrict__ C, int ldc, long long bsC,
    int M, int K,
    __half* __restrict__ scal)
{
    extern __shared__ __half smh[];
    const uint32_t sb = smem_u32(smh);

    A += (size_t)blockIdx.z * bsA;
    C += (size_t)blockIdx.z * bsC;

    const int tid  = threadIdx.x;
    const int w    = tid >> 5;
    const int lane = tid & 31;
    const int g    = lane >> 2;
    const int tg   = lane & 3;
    const int wm   = (w & 1) * 64;
    const int wn   = (w >> 1) * 64;
    const int rowBase = blockIdx.y * 128;
    const int colBase = blockIdx.x * 128;
    const int T = K >> 5;

    auto load_stage = [&](int s, int kt) {
        const int k0 = kt << 5;
        const uint32_t ab = sb + (uint32_t)(s * STAGE_HALVES) * 2u;
        const uint32_t bb = ab + TILE_HALVES * 2u;
#pragma unroll
        for (int i = 0; i < 4; i++) {
            int flat = i * 128 + tid;
            int r = flat >> 2;
            int c = flat & 3;
            uint32_t so = (uint32_t)(r * 40 + c * 8) * 2u;
            int gr = rowBase + r;
            const __half* srcA = A + (size_t)(gr < M ? gr : 0) * lda + k0 + c * 8;
            cp16(ab + so, srcA, gr < M ? 16 : 0);
            const __half* srcB = Bp + (size_t)(colBase + r) * K + k0 + c * 8;
            cp16(bb + so, srcB, 16);
        }
        asm volatile("cp.async.commit_group;" ::: "memory");
    };

    float acc[4][8][4];
#pragma unroll
    for (int mt = 0; mt < 4; mt++)
#pragma unroll
        for (int nt = 0; nt < 8; nt++)
#pragma unroll
            for (int i = 0; i < 4; i++) acc[mt][nt][i] = 0.0f;

    load_stage(0, 0);
    load_stage(1, 1);

    for (int kt = 0; kt < T; kt++) {
        const int s = kt % 3;
        if (kt + 1 < T) asm volatile("cp.async.wait_group 1;" ::: "memory");
        else            asm volatile("cp.async.wait_group 0;" ::: "memory");
        __syncthreads();
        if (kt + 2 < T) load_stage((kt + 2) % 3, kt + 2);

        const uint32_t* aw = reinterpret_cast<const uint32_t*>(smh + s * STAGE_HALVES);
        const uint32_t* bw = aw + (TILE_HALVES / 2);
#pragma unroll
        for (int kf = 0; kf < 2; kf++) {
            const int kb = kf * 8;
            unsigned a[4][4], b[8][2];
#pragma unroll
            for (int mt = 0; mt < 4; mt++) {
                const uint32_t* ap = aw + (wm + mt * 16 + g) * 20 + kb + tg;
                a[mt][0] = ap[0];
                a[mt][1] = ap[8 * 20];
                a[mt][2] = ap[4];
                a[mt][3] = ap[8 * 20 + 4];
            }
#pragma unroll
            for (int nt = 0; nt < 8; nt++) {
                const uint32_t* bp = bw + (wn + nt * 8 + g) * 20 + kb + tg;
                b[nt][0] = bp[0];
                b[nt][1] = bp[4];
            }
#pragma unroll
            for (int mt = 0; mt < 4; mt++)
#pragma unroll
                for (int nt = 0; nt < 8; nt++)
                    MMA16816(acc[mt][nt], a[mt][0], a[mt][1], a[mt][2], a[mt][3],
                             b[nt][0], b[nt][1]);
        }
        __syncthreads();
    }

    // ---- Epilogue ----
#pragma unroll
    for (int mt = 0; mt < 4; mt++) {
        int r0 = rowBase + wm + mt * 16 + g;
#pragma unroll
        for (int nt = 0; nt < 8; nt++) {
            int c0 = colBase + wn + nt * 8 + 2 * tg;
            float2 lo = make_float2(acc[mt][nt][0], acc[mt][nt][1]);
            float2 hi = make_float2(acc[mt][nt][2], acc[mt][nt][3]);
            if (MODE >= 1) {
                lo.x = silu_f(lo.x); lo.y = silu_f(lo.y);
                hi.x = silu_f(hi.x); hi.y = silu_f(hi.y);
            }
            if (MODE == 2) {
                if (colBase < 384) {
                    // scal *= gate, in place (each element owned by one thread)
                    if (r0 < M) {
                        __half2* p = reinterpret_cast<__half2*>(scal + (size_t)r0 * 384 + c0);
                        float2 o = __half22float2(*p);
                        *p = __floats2half2_rn(o.x * lo.x, o.y * lo.y);
                    }
                    if (r0 + 8 < M) {
                        __half2* p = reinterpret_cast<__half2*>(scal + (size_t)(r0 + 8) * 384 + c0);
                        float2 o = __half22float2(*p);
                        *p = __floats2half2_rn(o.x * hi.x, o.y * hi.y);
                    }
                } else {
                    int cg = c0 - 384;
                    if (r0 < M)
                        *reinterpret_cast<__half2*>(C + (size_t)r0 * 256 + cg) =
                            __float22half2_rn(lo);
                    if (r0 + 8 < M)
                        *reinterpret_cast<__half2*>(C + (size_t)(r0 + 8) * 256 + cg) =
                            __float22half2_rn(hi);
                }
            } else {
                if (r0 < M) {
                    OT* cr = C + (size_t)r0 * ldc + c0;
                    if (sizeof(OT) == 2) *reinterpret_cast<__half2*>(cr) = __float22half2_rn(lo);
                    else                 *reinterpret_cast<float2*>(cr) = lo;
                }
                if (r0 + 8 < M) {
                    OT* cr = C + (size_t)(r0 + 8) * ldc + c0;
                    if (sizeof(OT) == 2) *reinterpret_cast<__half2*>(cr) = __float22half2_rn(hi);
                    else                 *reinterpret_cast<float2*>(cr) = hi;
                }
            }
        }
    }
}

// ---------------------------------------------------------------------------
// K4: build gated vec planes from x and vector gates (gates is [n,256]).
// ---------------------------------------------------------------------------
__global__ void gate_prep_kernel(const float* __restrict__ x, const __half* __restrict__ gates,
                                 __half* __restrict__ vg, int n) {
    int idx = blockIdx.x * blockDim.x + threadIdx.x;
    if (idx >= n * 128) return;
    int row = idx >> 7;
    int u = idx & 127;
    const __half* gr = gates + (size_t)row * 256;
    const float* xr = x + (size_t)row * 512;
    float s  = xr[u];
    float g1 = __half2float(gr[u]);
    float c2 = SQ2F * s * __half2float(gr[128 + u]);
#pragma unroll
    for (int i = 0; i < 3; i++) {
        float vi = xr[128 + u * 3 + i];
        __half* vgp = vg + ((size_t)i * n + row) * 256;
        vgp[u]       = __float2half(vi * g1);
        vgp[128 + u] = __float2half(vi * c2);
    }
}

// ---------------------------------------------------------------------------
// K7: residuals + scalar layernorm + vector RMS norm, write output [n,512].
// outs/outv are fp16; all norm math fp32.
// ---------------------------------------------------------------------------
__global__ void finalize_kernel(const float* __restrict__ x, const __half* __restrict__ outs,
                                const __half* __restrict__ outv, float* __restrict__ out, int n) {
    int gw = (int)((blockIdx.x * blockDim.x + threadIdx.x) >> 5);
    int lane = threadIdx.x & 31;
    if (gw >= n) return;
    const float* xr = x + (size_t)gw * 512;
    float* orow = out + (size_t)gw * 512;

    float so[4];
    float sum = 0.f;
#pragma unroll
    for (int t = 0; t < 4; t++) {
        int u = lane + 32 * t;
        so[t] = __half2float(outs[(size_t)gw * 128 + u]) + xr[u];
        sum += so[t];
    }
#pragma unroll
    for (int o = 16; o > 0; o >>= 1) sum += __shfl_xor_sync(0xffffffffu, sum, o);
    float mean = sum * (1.0f / 128.0f);
    float ssum = 0.f;
#pragma unroll
    for (int t = 0; t < 4; t++) {
        so[t] -= mean;
        ssum += so[t] * so[t];
    }
#pragma unroll
    for (int o = 16; o > 0; o >>= 1) ssum += __shfl_xor_sync(0xffffffffu, ssum, o);
    float inv = 1.0f / (sqrtf(ssum * (1.0f / 128.0f)) + 1e-6f);
#pragma unroll
    for (int t = 0; t < 4; t++) orow[lane + 32 * t] = so[t] * inv;

    float vo[4][3];
    float vs = 0.f;
#pragma unroll
    for (int t = 0; t < 4; t++) {
        int u = lane + 32 * t;
#pragma unroll
        for (int i = 0; i < 3; i++) {
            vo[t][i] = __half2float(outv[((size_t)i * n + gw) * 128 + u]) + xr[128 + u * 3 + i];
            vs += vo[t][i] * vo[t][i];
        }
    }
#pragma unroll
    for (int o = 16; o > 0; o >>= 1) vs += __shfl_xor_sync(0xffffffffu, vs, o);
    float vinv = 1.0f / (sqrtf(vs * (1.0f / 128.0f)) + 1e-6f);
#pragma unroll
    for (int t = 0; t < 4; t++) {
        int u = lane + 32 * t;
#pragma unroll
        for (int i = 0; i < 3; i++)
            orow[128 + u * 3 + i] = vo[t][i] * vinv;
    }
}

// ---------------------------------------------------------------------------
extern "C" void kernel_launch(void* const* d_in, const int* in_sizes, int n_in,
                              void* d_out, int out_size) {
    const float* x  = (const float*)d_in[0];
    const float* W1 = (const float*)d_in[1];   // [384,384]
    const float* W2 = (const float*)d_in[2];   // [384,768] (cols 640:768 dead)
    const float* Ws = (const float*)d_in[3];   // [384,128]
    const float* Wv = (const float*)d_in[4];   // [256,128]
    float* out = (float*)d_out;
    int n = in_sizes[0] / 512;

    __half *scal, *h, *gates, *vg, *outs, *outv, *w1p, *w2p, *wsp, *wvp;
    cudaGetSymbolAddress((void**)&scal,  g_scal);
    cudaGetSymbolAddress((void**)&h,     g_h);
    cudaGetSymbolAddress((void**)&gates, g_gates);
    cudaGetSymbolAddress((void**)&vg,    g_vg);
    cudaGetSymbolAddress((void**)&outs,  g_outs);
    cudaGetSymbolAddress((void**)&outv,  g_outv);
    cudaGetSymbolAddress((void**)&w1p,   g_w1p);
    cudaGetSymbolAddress((void**)&w2p,   g_w2p);
    cudaGetSymbolAddress((void**)&wsp,   g_wsp);
    cudaGetSymbolAddress((void**)&wvp,   g_wvp);

    const int SMEM_BYTES = 3 * STAGE_HALVES * 2;   // 61440
    cudaFuncSetAttribute((const void*)gemm_fp16_kernel<1, __half>,
                         cudaFuncAttributeMaxDynamicSharedMemorySize, SMEM_BYTES);
    cudaFuncSetAttribute((const void*)gemm_fp16_kernel<2, __half>,
                         cudaFuncAttributeMaxDynamicSharedMemorySize, SMEM_BYTES);
    cudaFuncSetAttribute((const void*)gemm_fp16_kernel<0, __half>,
                         cudaFuncAttributeMaxDynamicSharedMemorySize, SMEM_BYTES);

    int mblocks = (n + 127) / 128;

    // Pack weights -> [N,K] K-major fp16.
    pack_w_kernel<<<(384 * 384 + 255) / 256, 256>>>(W1, w1p, 384, 384, 384);
    pack_w_kernel<<<(640 * 384 + 255) / 256, 256>>>(W2, w2p, 384, 640, 768);
    pack_w_kernel<<<(128 * 384 + 255) / 256, 256>>>(Ws, wsp, 384, 128, 128);
    pack_w_kernel<<<(128 * 256 + 255) / 256, 256>>>(Wv, wvp, 256, 128, 128);

    // K1: scal features (fp16)
    prep_scal_kernel<<<(n * 128 + 255) / 256, 256>>>(x, scal, n);

    // G1: h = silu(scal @ W1) -> fp16
    dim3 g1(3, mblocks, 1);
    gemm_fp16_kernel<1, __half><<<g1, 128, SMEM_BYTES>>>(
        scal, 384, 0LL, w1p, h, 384, 0LL, n, 384, nullptr);

    // G2 fused: col tiles 0-2 gate scal in place; tiles 3-4 write gates[n,256]
    dim3 g2(5, mblocks, 1);
    gemm_fp16_kernel<2, __half><<<g2, 128, SMEM_BYTES>>>(
        h, 384, 0LL, w2p, gates, 256, 0LL, n, 384, scal);

    // K4: build vg planes from x and vector gates
    gate_prep_kernel<<<(n * 128 + 255) / 256, 256>>>(x, gates, vg, n);

    // G5: outs = scal_gated @ Ws -> fp16
    dim3 g5(1, mblocks, 1);
    gemm_fp16_kernel<0, __half><<<g5, 128, SMEM_BYTES>>>(
        scal, 384, 0LL, wsp, outs, 128, 0LL, n, 384, nullptr);

    // G6: outv_i = vg_i @ Wv (3 planes over z) -> fp16
    dim3 g6(1, mblocks, 3);
    gemm_fp16_kernel<0, __half><<<g6, 128, SMEM_BYTES>>>(
        vg, 256, (long long)n * 256, wvp, outv, 128, (long long)n * 128, n, 256, nullptr);

    // K7: residual + norms + output
    finalize_kernel<<<(n + 7) / 8, 256>>>(x, outs, outv, out, n);
}